// round 15
// baseline (speedup 1.0000x reference)
#include <cuda_runtime.h>
#include <cuda_bf16.h>
#include <math.h>

// DescriptorBuilder: periodic minimum-image descriptors (O(N^2) factorized).
// Radial:  q_r[i,k] = sum_j fc(r_ij) * r_ij^k, k=0..8
// Angular: q_ang[i,n,0] = S_n^2, S_n = sum_j fc r^n
//          q_ang[i,n,1] = |V_n|^2, V_n = sum_j fc r^(n-1) dr
//          q_ang[i,n,2] = 0.5*(3*||M_n||_F^2 - S_n^2), M_n = sum_j fc r^(n-2) dr(x)dr
//
// Lean shell (R8/R14): 128 threads/block, 2 warps per atom, 2 atoms/block,
// 96 blocks = one wave; float4 staging; diag-box fast path; N==192
// specialization; full butterfly; sub==1 publish; 18-lane epilogue.
// NEW: trace identity tr(M_n) = S_n eliminates the zz accumulator of each
// M_n (M_zz = S_n - M_xx - M_yy in the epilogue): 33 accumulators instead
// of 36 -> 3 fewer FMAs/pair, 15 fewer butterfly shuffles.
//
// Accumulator layout: [0..8] radial (S_n = acc[n]); [9..17] V_n (3x3);
// [18+5n .. 22+5n] M_n as (xx, xy, xz, yy, yz) — zz derived.

#define BLOCK 128
#define MAXN 512
#define RCUT 6.0f

__global__ void __launch_bounds__(BLOCK)
desc_kernel(const float* __restrict__ R,
            const float* __restrict__ box,
            float* __restrict__ out, int N)
{
    __shared__ float sR[MAXN * 3];    // flat raw Cartesian coords
    __shared__ float sred[2][33];     // partial sums published by sub==1 warps

    const int t    = threadIdx.x;
    const int lane = t & 31;
    const int warp = t >> 5;        // 0..3
    const int a    = warp >> 1;     // atom slot (0/1)
    const int sub  = warp & 1;      // j-range half
    const int i    = blockIdx.x * 2 + a;
    const bool valid = (i < N);

    // ---- Vectorized staging: 3N floats via float4 ----
    {
        const int nflt = 3 * N;
        const int nvec = nflt >> 2;
        const float4* R4 = reinterpret_cast<const float4*>(R);
        float4* s4 = reinterpret_cast<float4*>(sR);
        for (int v = t; v < nvec; v += BLOCK) s4[v] = __ldg(R4 + v);
        for (int v = (nvec << 2) + t; v < nflt; v += BLOCK) sR[v] = __ldg(R + v);
    }

    // Box in registers; diagonal fast path avoids the 3x3 inverse.
    float b[9];
#pragma unroll
    for (int k = 0; k < 9; k++) b[k] = __ldg(box + k);

    const bool diag = (b[1] == 0.f && b[2] == 0.f && b[3] == 0.f &&
                       b[5] == 0.f && b[6] == 0.f && b[7] == 0.f);

    float inv[9];
    if (diag) {
        inv[0] = 1.0f / b[0];
        inv[4] = 1.0f / b[4];
        inv[8] = 1.0f / b[8];
    } else {
        const float det =
            b[0] * (b[4] * b[8] - b[5] * b[7]) -
            b[1] * (b[3] * b[8] - b[5] * b[6]) +
            b[2] * (b[3] * b[7] - b[4] * b[6]);
        const float idet = 1.0f / det;
        inv[0] = (b[4] * b[8] - b[5] * b[7]) * idet;
        inv[1] = (b[2] * b[7] - b[1] * b[8]) * idet;
        inv[2] = (b[1] * b[5] - b[2] * b[4]) * idet;
        inv[3] = (b[5] * b[6] - b[3] * b[8]) * idet;
        inv[4] = (b[0] * b[8] - b[2] * b[6]) * idet;
        inv[5] = (b[2] * b[3] - b[0] * b[5]) * idet;
        inv[6] = (b[3] * b[7] - b[4] * b[6]) * idet;
        inv[7] = (b[1] * b[6] - b[0] * b[7]) * idet;
        inv[8] = (b[0] * b[4] - b[1] * b[3]) * idet;
    }

    __syncthreads();   // staging complete

    const float PI_OVER_RC = 3.14159265358979323846f / RCUT;

    float acc[33];
#pragma unroll
    for (int k = 0; k < 33; k++) acc[k] = 0.0f;

    if (valid) {
        const float rix = sR[3 * i + 0];
        const float riy = sR[3 * i + 1];
        const float riz = sR[3 * i + 2];
        const int j0 = lane + 32 * sub;

        auto body = [&](float cx, float cy, float cz, bool skip) {
            float dx, dy, dz;
            if (diag) {
                dx = cx - b[0] * rintf(inv[0] * cx);
                dy = cy - b[4] * rintf(inv[4] * cy);
                dz = cz - b[8] * rintf(inv[8] * cz);
            } else {
                float f0 = rintf(inv[0] * cx + inv[1] * cy + inv[2] * cz);
                float f1 = rintf(inv[3] * cx + inv[4] * cy + inv[5] * cz);
                float f2 = rintf(inv[6] * cx + inv[7] * cy + inv[8] * cz);
                dx = cx - (b[0] * f0 + b[1] * f1 + b[2] * f2);
                dy = cy - (b[3] * f0 + b[4] * f1 + b[5] * f2);
                dz = cz - (b[6] * f0 + b[7] * f1 + b[8] * f2);
            }
            float r2 = dx * dx + dy * dy + dz * dz;
            float invr = rsqrtf(r2);
            float r = r2 * invr;
            if (skip || r >= RCUT) return;   // fc exactly 0 at/beyond cutoff

            float fc = 0.5f * __cosf(r * PI_OVER_RC) + 0.5f;

            // Radial moments fc * r^k, k = 0..8 (log-depth powers)
            float rr2 = r * r;
            float rr3 = rr2 * r;
            float rr4 = rr2 * rr2;
            float fcr4 = fc * rr4;
            acc[0] += fc;
            acc[1] += fc * r;
            acc[2] += fc * rr2;
            acc[3] += fc * rr3;
            acc[4] += fcr4;
            acc[5] += fcr4 * r;
            acc[6] += fcr4 * rr2;
            acc[7] += fcr4 * rr3;
            acc[8] += fcr4 * rr4;

            // Angular weights: wv_n = fc r^(n-1), wm_n = fc r^(n-2)
            float wv0 = fc * invr;
            float wv2 = fc * r;
            float wm0 = wv0 * invr;
            float xx = dx * dx, xy = dx * dy, xz = dx * dz;
            float yy = dy * dy, yz = dy * dz;
            // zz dropped: tr(M_n) = S_n recovers it in the epilogue.

            acc[9]  += wv0 * dx;  acc[10] += wv0 * dy;  acc[11] += wv0 * dz;
            acc[12] += fc  * dx;  acc[13] += fc  * dy;  acc[14] += fc  * dz;
            acc[15] += wv2 * dx;  acc[16] += wv2 * dy;  acc[17] += wv2 * dz;

            acc[18] += wm0 * xx;  acc[19] += wm0 * xy;  acc[20] += wm0 * xz;
            acc[21] += wm0 * yy;  acc[22] += wm0 * yz;
            acc[23] += wv0 * xx;  acc[24] += wv0 * xy;  acc[25] += wv0 * xz;
            acc[26] += wv0 * yy;  acc[27] += wv0 * yz;
            acc[28] += fc  * xx;  acc[29] += fc  * xy;  acc[30] += fc  * xz;
            acc[31] += fc  * yy;  acc[32] += fc  * yz;
        };

        if (N == 192) {
            // Exactly 3 iterations per lane: batch all 9 LDS up front.
            const int ja = j0, jb = j0 + 64, jc = j0 + 128;
            float ax = sR[3 * ja], ay = sR[3 * ja + 1], az = sR[3 * ja + 2];
            float bx = sR[3 * jb], by = sR[3 * jb + 1], bz = sR[3 * jb + 2];
            float cx_ = sR[3 * jc], cy_ = sR[3 * jc + 1], cz_ = sR[3 * jc + 2];
            body(rix - ax,  riy - ay,  riz - az,  ja == i);
            body(rix - bx,  riy - by,  riz - bz,  jb == i);
            body(rix - cx_, riy - cy_, riz - cz_, jc == i);
        } else {
            for (int j = j0; j < N; j += 64) {
                body(rix - sR[3 * j], riy - sR[3 * j + 1], riz - sR[3 * j + 2],
                     j == i);
            }
        }

        // Full warp butterfly over 33 accumulators (165 shuffles).
#pragma unroll
        for (int k = 0; k < 33; k++) {
            float v = acc[k];
#pragma unroll
            for (int o = 16; o > 0; o >>= 1) v += __shfl_xor_sync(0xffffffffu, v, o);
            acc[k] = v;
        }
    }

    // Cross-warp combine: sub==1 warp publishes its 33 sums.
    if (sub == 1) {
        if (lane < 33) sred[a][lane] = acc[lane];
        if (lane == 0) sred[a][32] = acc[32];
    }
    __syncthreads();

    // Epilogue: 18 lanes of the sub==0 warp combine + write.
    if (valid && sub == 0 && lane < 18) {
#pragma unroll
        for (int k = 0; k < 33; k++) acc[k] += sred[a][k];   // broadcast LDS

        float val;
        if (lane < 9) {
            val = acc[lane];
        } else {
            int idx = lane - 9;
            int n = idx / 3;
            int l = idx - 3 * n;
            float s = acc[n];
            if (l == 0) {
                val = s * s;
            } else if (l == 1) {
                float vx = acc[9 + 3 * n], vy = acc[10 + 3 * n], vz = acc[11 + 3 * n];
                val = vx * vx + vy * vy + vz * vz;
            } else {
                float m0 = acc[18 + 5 * n], m1 = acc[19 + 5 * n], m2 = acc[20 + 5 * n];
                float m3 = acc[21 + 5 * n], m4 = acc[22 + 5 * n];
                float m5 = s - m0 - m3;      // zz from trace identity
                float frob = m0 * m0 + m3 * m3 + m5 * m5 +
                             2.0f * (m1 * m1 + m2 * m2 + m4 * m4);
                val = 0.5f * (3.0f * frob - s * s);
            }
        }
        out[(size_t)i * 18 + lane] = val;
    }
}

extern "C" void kernel_launch(void* const* d_in, const int* in_sizes, int n_in,
                              void* d_out, int out_size) {
    const float* R   = (const float*)d_in[0];   // [N,3] fp32
    // d_in[1] = Z (int32), unused by the reference math
    const float* box = (const float*)d_in[2];   // [3,3] fp32
    float* out = (float*)d_out;                 // [N,18] fp32
    const int N = in_sizes[0] / 3;
    const int blocks = (N + 1) / 2;             // 2 atoms per block
    desc_kernel<<<blocks, BLOCK>>>(R, box, out, N);
}

// round 16
// speedup vs baseline: 1.3413x; 1.3413x over previous
#include <cuda_runtime.h>
#include <cuda_bf16.h>
#include <math.h>

// DescriptorBuilder: periodic minimum-image descriptors (O(N^2) factorized).
// Radial:  q_r[i,k] = sum_j fc(r_ij) * r_ij^k, k=0..8
// Angular: q_ang[i,n,0] = S_n^2, S_n = sum_j fc r^n
//          q_ang[i,n,1] = |V_n|^2, V_n = sum_j fc r^(n-1) dr
//          q_ang[i,n,2] = 0.5*(3*||M_n||_F^2 - S_n^2), M_n = sum_j fc r^(n-2) dr(x)dr
//
// Leanest correct configuration (session final): 128 threads/block, 2 warps
// per atom (split j-range), 2 atoms/block, 96 blocks = one wave; float4
// staging; diag-box fast path; N==192 specialization with batched LDS;
// trace identity tr(M_n)=S_n drops the zz accumulators (33 total, 76 regs);
// full warp butterfly; sub==1 publish; 18-lane distributed epilogue.
// Harness timing is bimodal (~6.6us fast draw / ~8.9us slow draw) for
// identical binaries; this body minimizes time on either draw.

#define BLOCK 128
#define MAXN 512
#define RCUT 6.0f

__global__ void __launch_bounds__(BLOCK)
desc_kernel(const float* __restrict__ R,
            const float* __restrict__ box,
            float* __restrict__ out, int N)
{
    __shared__ float sR[MAXN * 3];    // flat raw Cartesian coords
    __shared__ float sred[2][33];     // partial sums published by sub==1 warps

    const int t    = threadIdx.x;
    const int lane = t & 31;
    const int warp = t >> 5;        // 0..3
    const int a    = warp >> 1;     // atom slot (0/1)
    const int sub  = warp & 1;      // j-range half
    const int i    = blockIdx.x * 2 + a;
    const bool valid = (i < N);

    // ---- Vectorized staging: 3N floats via float4 ----
    {
        const int nflt = 3 * N;
        const int nvec = nflt >> 2;
        const float4* R4 = reinterpret_cast<const float4*>(R);
        float4* s4 = reinterpret_cast<float4*>(sR);
        for (int v = t; v < nvec; v += BLOCK) s4[v] = __ldg(R4 + v);
        for (int v = (nvec << 2) + t; v < nflt; v += BLOCK) sR[v] = __ldg(R + v);
    }

    // Box in registers; diagonal fast path avoids the 3x3 inverse.
    float b[9];
#pragma unroll
    for (int k = 0; k < 9; k++) b[k] = __ldg(box + k);

    const bool diag = (b[1] == 0.f && b[2] == 0.f && b[3] == 0.f &&
                       b[5] == 0.f && b[6] == 0.f && b[7] == 0.f);

    float inv[9];
    if (diag) {
        inv[0] = 1.0f / b[0];
        inv[4] = 1.0f / b[4];
        inv[8] = 1.0f / b[8];
    } else {
        const float det =
            b[0] * (b[4] * b[8] - b[5] * b[7]) -
            b[1] * (b[3] * b[8] - b[5] * b[6]) +
            b[2] * (b[3] * b[7] - b[4] * b[6]);
        const float idet = 1.0f / det;
        inv[0] = (b[4] * b[8] - b[5] * b[7]) * idet;
        inv[1] = (b[2] * b[7] - b[1] * b[8]) * idet;
        inv[2] = (b[1] * b[5] - b[2] * b[4]) * idet;
        inv[3] = (b[5] * b[6] - b[3] * b[8]) * idet;
        inv[4] = (b[0] * b[8] - b[2] * b[6]) * idet;
        inv[5] = (b[2] * b[3] - b[0] * b[5]) * idet;
        inv[6] = (b[3] * b[7] - b[4] * b[6]) * idet;
        inv[7] = (b[1] * b[6] - b[0] * b[7]) * idet;
        inv[8] = (b[0] * b[4] - b[1] * b[3]) * idet;
    }

    __syncthreads();   // staging complete

    const float PI_OVER_RC = 3.14159265358979323846f / RCUT;

    // Accumulators: [0..8] radial (S_n = acc[n]); [9..17] V_n (3x3);
    // [18+5n .. 22+5n] M_n as (xx, xy, xz, yy, yz) — zz via trace identity.
    float acc[33];
#pragma unroll
    for (int k = 0; k < 33; k++) acc[k] = 0.0f;

    if (valid) {
        const float rix = sR[3 * i + 0];
        const float riy = sR[3 * i + 1];
        const float riz = sR[3 * i + 2];
        const int j0 = lane + 32 * sub;

        auto body = [&](float cx, float cy, float cz, bool skip) {
            float dx, dy, dz;
            if (diag) {
                dx = cx - b[0] * rintf(inv[0] * cx);
                dy = cy - b[4] * rintf(inv[4] * cy);
                dz = cz - b[8] * rintf(inv[8] * cz);
            } else {
                float f0 = rintf(inv[0] * cx + inv[1] * cy + inv[2] * cz);
                float f1 = rintf(inv[3] * cx + inv[4] * cy + inv[5] * cz);
                float f2 = rintf(inv[6] * cx + inv[7] * cy + inv[8] * cz);
                dx = cx - (b[0] * f0 + b[1] * f1 + b[2] * f2);
                dy = cy - (b[3] * f0 + b[4] * f1 + b[5] * f2);
                dz = cz - (b[6] * f0 + b[7] * f1 + b[8] * f2);
            }
            float r2 = dx * dx + dy * dy + dz * dz;
            float invr = rsqrtf(r2);
            float r = r2 * invr;
            if (skip || r >= RCUT) return;   // fc exactly 0 at/beyond cutoff

            float fc = 0.5f * __cosf(r * PI_OVER_RC) + 0.5f;

            // Radial moments fc * r^k, k = 0..8 (log-depth powers)
            float rr2 = r * r;
            float rr3 = rr2 * r;
            float rr4 = rr2 * rr2;
            float fcr4 = fc * rr4;
            acc[0] += fc;
            acc[1] += fc * r;
            acc[2] += fc * rr2;
            acc[3] += fc * rr3;
            acc[4] += fcr4;
            acc[5] += fcr4 * r;
            acc[6] += fcr4 * rr2;
            acc[7] += fcr4 * rr3;
            acc[8] += fcr4 * rr4;

            // Angular weights: wv_n = fc r^(n-1), wm_n = fc r^(n-2)
            float wv0 = fc * invr;
            float wv2 = fc * r;
            float wm0 = wv0 * invr;
            float xx = dx * dx, xy = dx * dy, xz = dx * dz;
            float yy = dy * dy, yz = dy * dz;
            // zz dropped: tr(M_n) = S_n recovers it in the epilogue.

            acc[9]  += wv0 * dx;  acc[10] += wv0 * dy;  acc[11] += wv0 * dz;
            acc[12] += fc  * dx;  acc[13] += fc  * dy;  acc[14] += fc  * dz;
            acc[15] += wv2 * dx;  acc[16] += wv2 * dy;  acc[17] += wv2 * dz;

            acc[18] += wm0 * xx;  acc[19] += wm0 * xy;  acc[20] += wm0 * xz;
            acc[21] += wm0 * yy;  acc[22] += wm0 * yz;
            acc[23] += wv0 * xx;  acc[24] += wv0 * xy;  acc[25] += wv0 * xz;
            acc[26] += wv0 * yy;  acc[27] += wv0 * yz;
            acc[28] += fc  * xx;  acc[29] += fc  * xy;  acc[30] += fc  * xz;
            acc[31] += fc  * yy;  acc[32] += fc  * yz;
        };

        if (N == 192) {
            // Exactly 3 iterations per lane: batch all 9 LDS up front.
            const int ja = j0, jb = j0 + 64, jc = j0 + 128;
            float ax = sR[3 * ja], ay = sR[3 * ja + 1], az = sR[3 * ja + 2];
            float bx = sR[3 * jb], by = sR[3 * jb + 1], bz = sR[3 * jb + 2];
            float cx_ = sR[3 * jc], cy_ = sR[3 * jc + 1], cz_ = sR[3 * jc + 2];
            body(rix - ax,  riy - ay,  riz - az,  ja == i);
            body(rix - bx,  riy - by,  riz - bz,  jb == i);
            body(rix - cx_, riy - cy_, riz - cz_, jc == i);
        } else {
            for (int j = j0; j < N; j += 64) {
                body(rix - sR[3 * j], riy - sR[3 * j + 1], riz - sR[3 * j + 2],
                     j == i);
            }
        }

        // Full warp butterfly over 33 accumulators (165 shuffles).
#pragma unroll
        for (int k = 0; k < 33; k++) {
            float v = acc[k];
#pragma unroll
            for (int o = 16; o > 0; o >>= 1) v += __shfl_xor_sync(0xffffffffu, v, o);
            acc[k] = v;
        }
    }

    // Cross-warp combine: sub==1 warp publishes its 33 sums.
    if (sub == 1) {
        if (lane < 32) sred[a][lane] = acc[lane];
        if (lane == 0) sred[a][32] = acc[32];
    }
    __syncthreads();

    // Epilogue: 18 lanes of the sub==0 warp combine + write.
    if (valid && sub == 0 && lane < 18) {
#pragma unroll
        for (int k = 0; k < 33; k++) acc[k] += sred[a][k];   // broadcast LDS

        float val;
        if (lane < 9) {
            val = acc[lane];
        } else {
            int idx = lane - 9;
            int n = idx / 3;
            int l = idx - 3 * n;
            float s = acc[n];
            if (l == 0) {
                val = s * s;
            } else if (l == 1) {
                float vx = acc[9 + 3 * n], vy = acc[10 + 3 * n], vz = acc[11 + 3 * n];
                val = vx * vx + vy * vy + vz * vz;
            } else {
                float m0 = acc[18 + 5 * n], m1 = acc[19 + 5 * n], m2 = acc[20 + 5 * n];
                float m3 = acc[21 + 5 * n], m4 = acc[22 + 5 * n];
                float m5 = s - m0 - m3;      // zz from trace identity
                float frob = m0 * m0 + m3 * m3 + m5 * m5 +
                             2.0f * (m1 * m1 + m2 * m2 + m4 * m4);
                val = 0.5f * (3.0f * frob - s * s);
            }
        }
        out[(size_t)i * 18 + lane] = val;
    }
}

extern "C" void kernel_launch(void* const* d_in, const int* in_sizes, int n_in,
                              void* d_out, int out_size) {
    const float* R   = (const float*)d_in[0];   // [N,3] fp32
    // d_in[1] = Z (int32), unused by the reference math
    const float* box = (const float*)d_in[2];   // [3,3] fp32
    float* out = (float*)d_out;                 // [N,18] fp32
    const int N = in_sizes[0] / 3;
    const int blocks = (N + 1) / 2;             // 2 atoms per block
    desc_kernel<<<blocks, BLOCK>>>(R, box, out, N);
}